// round 12
// baseline (speedup 1.0000x reference)
#include <cuda_runtime.h>
#include <cstdint>
#include <cstring>

// ============================================================================
// Sparse masked CNN pyramid (14 levels) + MLP head — round 12.
// convk: thread = 1 position x 8-ci slice, acc = all 32 co (f32x2 packed).
//   - 2 LDG.128/tap/thread (quad covers each feature row exactly once)
//   - rolled tap loop, 1-tap-ahead register prefetch, warp-uniform tap skip
//   - neighbor indices loaded 2.25/thread + distributed by shuffles
//   - swizzled weight smem (quad slices hit disjoint bank groups)
//   - quad reduce-scatter epilogue
// ============================================================================

#define CAP 131072
#define NLEV 14
#define IDX_TOTAL 5592407
#define F_ROWS 214359

__device__ __align__(16) float g_F[F_ROWS * 32];   // per-level feature regions
__device__ int   g_idx[IDX_TOTAL];
__device__ int   g_pos[NLEV * CAP];
__device__ int   g_cnt[NLEV];              // zero-init; main block0 re-zeroes
__device__ float g_pools[NLEV * 32];       // zero-init; main block0 re-zeroes
__device__ volatile unsigned g_bars[16];   // zeroed by build_all0 each replay

__constant__ int c_LS[NLEV]   = {2048,1024,512,256,128,64,32,16,8,4,2,1,1,1};
__constant__ int c_IOFS[NLEV] = {0,4194304,5242880,5505024,5570560,5586944,5591040,
                                 5592064,5592320,5592384,5592400,5592404,5592405,5592406};
__constant__ int c_CAPF[NLEV] = {49152,49152,49152,40960,20480,4096,1024,256,
                                 64,16,4,1,1,1};
__constant__ int c_FOFF[NLEV] = {0,49152,98304,147456,188416,208896,212992,214016,
                                 214272,214336,214352,214356,214357,214358};

#define FMA2(d, a, b, c) \
    asm("fma.rn.f32x2 %0, %1, %2, %3;" : "=l"(d) : "l"(a), "l"(b), "l"(c))
#define ADD2(d, a, b) \
    asm("add.rn.f32x2 %0, %1, %2;" : "=l"(d) : "l"(a), "l"(b))
#define PACK_DUP(d, a) \
    do { unsigned _u = __float_as_uint(a); \
         asm("mov.b64 %0, {%1, %1};" : "=l"(d) : "r"(_u)); } while (0)

__device__ __forceinline__ float2 upk(unsigned long long a) {
    float2 f; memcpy(&f, &a, 8); return f;
}

// ---- grid-wide barriers (per-epoch counters, reset by next build_all0) -------
__device__ __forceinline__ void gwait(int e, unsigned nb) {
    __syncthreads();
    if (threadIdx.x == 0) {
        __threadfence();
        atomicAdd((unsigned*)&g_bars[e], 1u);
        while (g_bars[e] < nb) __nanosleep(128);
        __threadfence();
    }
    __syncthreads();
}
__device__ __forceinline__ void garrive(int e) {
    __syncthreads();
    __threadfence();
    if (threadIdx.x == 0) atomicAdd((unsigned*)&g_bars[e], 1u);
}

// ---- block compaction step (1024-thread blocks only) -------------------------
__device__ __forceinline__ void emit(int level, bool act, int lin, int posword,
                                     int iofs, int cap, unsigned* bitdst) {
    __shared__ int ewcnt[32];
    __shared__ int ewbase[32];
    __shared__ int ebbase;
    int tid = threadIdx.x, wid = tid >> 5, lane = tid & 31;
    unsigned m = __ballot_sync(0xffffffffu, act);
    if (lane == 0) {
        ewcnt[wid] = __popc(m);
        if (bitdst) bitdst[wid] = m;
    }
    __syncthreads();
    if (tid < 32) {
        int cc = ewcnt[tid];
        int x = cc;
        #pragma unroll
        for (int o = 1; o < 32; o <<= 1) {
            int y = __shfl_up_sync(0xffffffffu, x, o);
            if (tid >= o) x += y;
        }
        ewbase[tid] = x - cc;
        if (tid == 31) ebbase = atomicAdd(&g_cnt[level], x);
    }
    __syncthreads();
    int idx = -1;
    if (act) {
        idx = ebbase + ewbase[wid] + __popc(m & ((1u << lane) - 1u));
        if (idx < cap) g_pos[level * CAP + idx] = posword;
        else idx = -1;
    }
    if (lin >= 0) g_idx[iofs + lin] = idx;
    __syncthreads();
}

__device__ __forceinline__ int getbit(const unsigned* a, int c) {
    return (a[c >> 5] >> (c & 31)) & 1;
}

// ---- build: levels 0..7; zero barrier counters --------------------------------
__global__ __launch_bounds__(1024) void build_all0(const float* __restrict__ mask) {
    if (blockIdx.x == 0 && threadIdx.x < 16) g_bars[threadIdx.x] = 0;

    __shared__ unsigned a0[512];
    __shared__ unsigned a1[128];
    __shared__ unsigned a2[32];
    __shared__ unsigned a3[8];
    __shared__ unsigned a4[32];
    __shared__ unsigned a5[32];
    __shared__ unsigned a6[32];
    int tid = threadIdx.x;
    int tx = blockIdx.x & 15, ty = blockIdx.x >> 4;

    for (int r = 0; r < 16; r++) {
        int c = r * 1024 + tid;
        int li = c >> 7, lj = c & 127;
        int i = ty * 128 + li, j = tx * 128 + lj;
        bool act = (mask[i * 2048 + j] != 0.0f);
        emit(0, act, i * 2048 + j, (i << 16) | j, c_IOFS[0], c_CAPF[0], a0 + r * 32);
    }
    unsigned* bits[8] = {a0, a1, a2, a3, a4, a5, a6, nullptr};
    #pragma unroll
    for (int L = 1; L <= 7; L++) {
        int t = 128 >> L;
        int cells = t * t;
        int chunks = (cells + 1023) >> 10;
        int tprev = t * 2;
        for (int r = 0; r < chunks; r++) {
            int c = r * 1024 + tid;
            bool act = false;
            int lin = -1, pw = 0;
            if (c < cells) {
                int li = c / t, lj = c - li * t;
                int c00 = (2 * li) * tprev + 2 * lj;
                const unsigned* pb = bits[L - 1];
                act = getbit(pb, c00) | getbit(pb, c00 + 1) |
                      getbit(pb, c00 + tprev) | getbit(pb, c00 + tprev + 1);
                int i = ty * t + li, j = tx * t + lj;
                lin = i * (2048 >> L) + j;
                pw = (i << 16) | j;
            }
            emit(L, act, lin, pw, c_IOFS[L], c_CAPF[L],
                 (L < 7) ? (bits[L] + r * 32) : nullptr);
        }
    }
}

// ---- persistent main kernel ---------------------------------------------------
__global__ __launch_bounds__(256, 3) void main_kernel(
    const float* __restrict__ x,  const float* __restrict__ w1,
    const float* __restrict__ ws,
    const float* __restrict__ wm1, const float* __restrict__ bm1,
    const float* __restrict__ wm2, const float* __restrict__ bm2,
    float* __restrict__ out) {
    __shared__ __align__(128) float sW[9216];
    __shared__ float spool[32];
    __shared__ unsigned sball[2];
    int tid = threadIdx.x, bid = blockIdx.x;
    int lane = tid & 31;
    unsigned nb_ = gridDim.x;

    // ================= phase 0: conv1 (all blocks) + build_top (last block) ===
    for (int t = tid; t < 800; t += 256) sW[t] = w1[t];
    if (tid < 32) spool[tid] = 0.f;
    __syncthreads();
    {
        int n = min(g_cnt[0], c_CAPF[0]);
        int gw = (bid * 256 + tid) >> 5;
        int nw = (int)nb_ * 8;
        float pl = 0.f;
        for (int p = gw; p < n; p += nw) {
            int pw = g_pos[p];
            int i = pw >> 16, j = pw & 0xffff;
            float acc = 0.f;
            #pragma unroll
            for (int dy = 0; dy < 5; dy++) {
                int r = i + dy - 2;
                bool rv = (unsigned)r < 2048u;
                #pragma unroll
                for (int dx = 0; dx < 5; dx++) {
                    int cc = j + dx - 2;
                    float xv = (rv && (unsigned)cc < 2048u) ? x[r * 2048 + cc] : 0.f;
                    acc = fmaf(xv, sW[(dy * 5 + dx) * 32 + lane], acc);
                }
            }
            acc = fmaxf(acc, 0.f);
            g_F[(size_t)p * 32 + lane] = acc;   // level-0 region
            pl += acc;
        }
        atomicAdd(&spool[lane], pl);
    }
    if (bid == nb_ - 1) {
        // build_top: levels 8..13 (cells <= 64)
        for (int k = 8; k < NLEV; k++) {
            int s = c_LS[k], sp = c_LS[k - 1];
            int cells = s * s;
            const int* Ip = g_idx + c_IOFS[k - 1];
            bool act = false;
            int pwv = 0;
            if (tid < cells) {
                int i = tid / s, j = tid - i * s;
                #pragma unroll
                for (int di = 0; di < 2; di++)
                    #pragma unroll
                    for (int dj = 0; dj < 2; dj++) {
                        int r = 2 * i + di, cc = 2 * j + dj;
                        if (r < sp && cc < sp && __ldcg(&Ip[r * sp + cc]) >= 0)
                            act = true;
                    }
                pwv = (i << 16) | j;
            }
            unsigned m = __ballot_sync(0xffffffffu, act);
            if (tid == 0)  sball[0] = m;
            if (tid == 32) sball[1] = m;
            __syncthreads();
            int cnt0 = __popc(sball[0]);
            int total = cnt0 + (cells > 32 ? __popc(sball[1]) : 0);
            if (tid == 0) g_cnt[k] = total;
            if (tid < cells) {
                int idx = -1;
                if (act) {
                    idx = (tid < 32 ? 0 : cnt0) + __popc(m & ((1u << (tid & 31)) - 1u));
                    g_pos[k * CAP + idx] = pwv;
                }
                g_idx[c_IOFS[k] + tid] = idx;
            }
            __syncthreads();
        }
    }
    __syncthreads();
    if (tid < 32) atomicAdd(&g_pools[tid], spool[tid]);
    __syncthreads();

    // ================= levels 1..7: ci-slice sparse conv =======================
    int s4  = tid & 3;             // quad slot: ci slice s4*8..s4*8+7
    int s8  = s4 * 8;              // float offset of ci slice in a feature row
    int pid = tid >> 2;            // 0..63 position within 64-pos tile
    int chb = (s4 & 1) * 16 + ((s4 >> 1) & 1) * 8;   // co slice after reduce-scatter
    int qbase = tid & ~3;          // first lane of this quad (within block==warp? use lane)
    int lbase = lane & ~3;         // quad base within warp (for shuffles)

    #pragma unroll 1
    for (int L = 1; L <= 7; L++) {
        // stage this level's weights with chunk swizzle + zero spool
        {
            const float* src = ws + (size_t)(L - 1) * 9216;
            for (int t = tid; t < 9216; t += 256) {
                int d = t >> 10, rem = t & 1023;
                int ci = rem >> 5, co = rem & 31;
                int slot = ((co >> 2) + 2 * (ci >> 3)) & 7;
                sW[d * 1024 + ci * 32 + slot * 4 + (co & 3)] = src[t];
            }
        }
        if (tid < 32) spool[tid] = 0.f;
        gwait(L - 1, nb_);         // previous phase complete grid-wide

        const float* __restrict__ Fp = g_F + (size_t)c_FOFF[L - 1] * 32;
        float* __restrict__ Fc = g_F + (size_t)c_FOFF[L] * 32;
        int sp = c_LS[L - 1];
        const int* __restrict__ Ip = g_idx + c_IOFS[L - 1];
        const int* __restrict__ posl = g_pos + L * CAP;
        int n = min(g_cnt[L], c_CAPF[L]);

        unsigned long long pool[4] = {0ull, 0ull, 0ull, 0ull};
        for (int base = bid * 64; base < n; base += (int)nb_ * 64) {
            int p = base + pid;
            int pw = (p < n) ? posl[p] : -1;
            int pi = pw >> 16, pj = pw & 0xffff;

            // lane r of quad loads neighbor indices for taps r, r+4 (+8 if r==0)
            int nA = -1, nB = -1, nC = -1;
            if (pw >= 0) {
                int dA = s4, dB = s4 + 4;
                int rA = 2 * pi + dA / 3 - 1, cA = 2 * pj + dA % 3 - 1;
                int rB = 2 * pi + dB / 3 - 1, cB = 2 * pj + dB % 3 - 1;
                if ((unsigned)rA < (unsigned)sp && (unsigned)cA < (unsigned)sp)
                    nA = Ip[rA * sp + cA];
                if ((unsigned)rB < (unsigned)sp && (unsigned)cB < (unsigned)sp)
                    nB = Ip[rB * sp + cB];
                if (s4 == 0) {
                    int rC = 2 * pi + 1, cC = 2 * pj + 1;
                    if ((unsigned)rC < (unsigned)sp && (unsigned)cC < (unsigned)sp)
                        nC = Ip[rC * sp + cC];
                }
            }

            unsigned long long acc[16];
            #pragma unroll
            for (int i2 = 0; i2 < 16; i2++) acc[i2] = 0ull;

            // prefetch tap 0 features (quad covers the 128B row once)
            bool curv;
            float4 c0, c1;
            {
                int q = __shfl_sync(0xffffffffu, nA, lbase);
                curv = q >= 0;
                const float* ap = Fp + (size_t)(curv ? q : 0) * 32 + s8;
                c0 = *(const float4*)ap;
                c1 = *(const float4*)(ap + 4);
            }
            #pragma unroll 1
            for (int d = 0; d < 9; d++) {
                // prefetch tap d+1
                bool nxv = false;
                float4 n0 = make_float4(0.f,0.f,0.f,0.f), n1 = n0;
                int dn = d + 1;
                if (dn < 9) {
                    int val = (dn < 4) ? nA : ((dn < 8) ? nB : nC);
                    int q = __shfl_sync(0xffffffffu, val, lbase | (dn & 3));
                    nxv = q >= 0;
                    const float* ap = Fp + (size_t)(nxv ? q : 0) * 32 + s8;
                    n0 = *(const float4*)ap;
                    n1 = *(const float4*)(ap + 4);
                }
                if (__ballot_sync(0xffffffffu, curv)) {
                    float4 a0 = curv ? c0 : make_float4(0.f,0.f,0.f,0.f);
                    float4 a1 = curv ? c1 : make_float4(0.f,0.f,0.f,0.f);
                    const float* wd = sW + d * 1024;
                    #pragma unroll
                    for (int j = 0; j < 8; j++) {
                        float e = (j == 0) ? a0.x : (j == 1) ? a0.y : (j == 2) ? a0.z
                                : (j == 3) ? a0.w : (j == 4) ? a1.x : (j == 5) ? a1.y
                                : (j == 6) ? a1.z : a1.w;
                        unsigned long long A;
                        PACK_DUP(A, e);
                        const ulonglong2* wr =
                            (const ulonglong2*)(wd + (s8 + j) * 32);
                        #pragma unroll
                        for (int k = 0; k < 8; k++) {
                            ulonglong2 w = wr[(k + 2 * s4) & 7];
                            FMA2(acc[2*k],   A, w.x, acc[2*k]);
                            FMA2(acc[2*k+1], A, w.y, acc[2*k+1]);
                        }
                    }
                }
                c0 = n0; c1 = n1; curv = nxv;
            }

            // quad reduce-scatter: xor1 keeps 16 co, xor2 keeps 8 co
            unsigned long long h[8];
            #pragma unroll
            for (int k = 0; k < 8; k++) {
                unsigned long long t0 = __shfl_xor_sync(0xffffffffu, acc[k], 1);
                unsigned long long t1 = __shfl_xor_sync(0xffffffffu, acc[k+8], 1);
                unsigned long long a = (s4 & 1) ? acc[k+8] : acc[k];
                unsigned long long b = (s4 & 1) ? t1 : t0;
                ADD2(h[k], a, b);
            }
            unsigned long long qv[4];
            #pragma unroll
            for (int k = 0; k < 4; k++) {
                unsigned long long t0 = __shfl_xor_sync(0xffffffffu, h[k], 2);
                unsigned long long t1 = __shfl_xor_sync(0xffffffffu, h[k+4], 2);
                unsigned long long a = (s4 & 2) ? h[k+4] : h[k];
                unsigned long long b = (s4 & 2) ? t1 : t0;
                ADD2(qv[k], a, b);
            }
            // relu (packed), pool, store this lane's 8-co slice
            #pragma unroll
            for (int k = 0; k < 4; k++) {
                float2 f = upk(qv[k]);
                f.x = fmaxf(f.x, 0.f); f.y = fmaxf(f.y, 0.f);
                unsigned long long P;
                asm("mov.b64 %0, {%1, %2};" : "=l"(P)
                    : "r"(__float_as_uint(f.x)), "r"(__float_as_uint(f.y)));
                ADD2(pool[k], P, pool[k]);
                qv[k] = P;
            }
            if (p < n) {
                ulonglong2* dst = (ulonglong2*)(Fc + (size_t)p * 32 + chb);
                dst[0] = make_ulonglong2(qv[0], qv[1]);
                dst[1] = make_ulonglong2(qv[2], qv[3]);
            }
        }
        // pool: butterfly (offsets 16,8,4 preserve lane&3 co-slice groups)
        #pragma unroll
        for (int k = 0; k < 4; k++) {
            #pragma unroll
            for (int off = 16; off >= 4; off >>= 1) {
                unsigned long long o = __shfl_xor_sync(0xffffffffu, pool[k], off);
                ADD2(pool[k], o, pool[k]);
            }
        }
        if (lane < 4) {
            #pragma unroll
            for (int k = 0; k < 4; k++) {
                float2 f = upk(pool[k]);
                atomicAdd(&spool[chb + 2*k],     f.x);
                atomicAdd(&spool[chb + 2*k + 1], f.y);
            }
        }
        __syncthreads();
        if (tid < 32) atomicAdd(&g_pools[L * 32 + tid], spool[tid]);
        __syncthreads();
    }

    // ================= tail: block 0 only ======================================
    if (bid != 0) { garrive(7); return; }
    gwait(7, nb_);

    int wid = tid >> 5;
    for (int k = 8; k < NLEV; k++) {
        int n = min(__ldcg(&g_cnt[k]), c_CAPF[k]);
        int sp = c_LS[k - 1];
        const int* Ip = g_idx + c_IOFS[k - 1];
        const float* FpT = g_F + (size_t)c_FOFF[k - 1] * 32;
        float* FcT = g_F + (size_t)c_FOFF[k] * 32;
        const float* W = ws + (size_t)(k - 1) * 9216;
        if (tid < 32) spool[tid] = 0.f;
        __syncthreads();
        float pl = 0.f;
        for (int p = wid; p < n; p += 8) {
            int pw = __ldcg(&g_pos[k * CAP + p]);
            int pi = pw >> 16, pj = pw & 0xffff;
            float acc = 0.f;
            for (int d = 0; d < 9; d++) {
                int r = 2 * pi + d / 3 - 1;
                int cc = 2 * pj + d % 3 - 1;
                if ((unsigned)r < (unsigned)sp && (unsigned)cc < (unsigned)sp) {
                    int nbv = __ldcg(&Ip[r * sp + cc]);
                    if (nbv >= 0) {
                        float row = __ldcg(&FpT[(size_t)nbv * 32 + lane]);
                        const float* wd = W + d * 1024;
                        #pragma unroll
                        for (int ci = 0; ci < 32; ci++)
                            acc = fmaf(__shfl_sync(0xffffffffu, row, ci),
                                       wd[ci * 32 + lane], acc);
                    }
                }
            }
            acc = fmaxf(acc, 0.f);
            FcT[(size_t)p * 32 + lane] = acc;
            pl += acc;
        }
        atomicAdd(&spool[lane], pl);
        __syncthreads();
        if (tid < 32) g_pools[k * 32 + tid] = spool[tid];
        __syncthreads();
    }

    // MLP: feat[448] -> 256 relu -> 128 (reuse sW as sf/sh)
    float* sf = sW;
    float* sh = sW + 448;
    for (int i = tid; i < 448; i += 256) {
        int k = i >> 5;
        float cnt = (float)max(__ldcg(&g_cnt[k]), 1);
        sf[i] = g_pools[i] / cnt;
    }
    __syncthreads();
    {
        float acc = bm1[tid];
        #pragma unroll 4
        for (int i = 0; i < 448; i++) acc = fmaf(sf[i], wm1[i * 256 + tid], acc);
        sh[tid] = fmaxf(acc, 0.f);
    }
    __syncthreads();
    if (tid < 128) {
        float acc = bm2[tid];
        #pragma unroll 4
        for (int j = 0; j < 256; j++) acc = fmaf(sh[j], wm2[j * 128 + tid], acc);
        out[tid] = acc;
    }

    // re-zero state for next replay (bars reset by next build_all0)
    __syncthreads();
    for (int i = tid; i < NLEV * 32; i += 256) g_pools[i] = 0.f;
    if (tid < NLEV) g_cnt[tid] = 0;
}

// ---- host launch ---------------------------------------------------------------
extern "C" void kernel_launch(void* const* d_in, const int* in_sizes, int n_in,
                              void* d_out, int out_size) {
    const float* x    = (const float*)d_in[0];
    const float* mask = (const float*)d_in[1];
    const float* w1   = (const float*)d_in[2];
    const float* ws   = (const float*)d_in[3];
    const float* wm1  = (const float*)d_in[4];
    const float* bm1  = (const float*)d_in[5];
    const float* wm2  = (const float*)d_in[6];
    const float* bm2  = (const float*)d_in[7];
    float* out = (float*)d_out;

    build_all0<<<256, 1024>>>(mask);

    int occ = 0, sms = 0;
    cudaOccupancyMaxActiveBlocksPerMultiprocessor(&occ, main_kernel, 256, 0);
    cudaDeviceGetAttribute(&sms, cudaDevAttrMultiProcessorCount, 0);
    int grid = occ * sms;
    if (grid > 592) grid = 592;
    if (grid < 1) grid = 1;

    main_kernel<<<grid, 256>>>(x, w1, ws, wm1, bm1, wm2, bm2, out);
}

// round 13
// speedup vs baseline: 1.3738x; 1.3738x over previous
#include <cuda_runtime.h>
#include <cstdint>
#include <cstring>

// ============================================================================
// Sparse masked CNN pyramid (14 levels) + MLP head — round 13.
// = R9 (best, 338us) + two isolated fixes:
//   (a) convk levels use contiguous balanced per-block chunks (no 2-tile
//       stragglers at L1/L2)
//   (b) tail levels 8..13 run on 8 blocks with mini grid-barriers
// ============================================================================

#define CAP 131072
#define NLEV 14
#define IDX_TOTAL 5592407

__device__ __align__(16) float g_FA[CAP * 32];
__device__ __align__(16) float g_FB[CAP * 32];
__device__ int   g_idx[IDX_TOTAL];
__device__ int   g_pos[NLEV * CAP];
__device__ int   g_cnt[NLEV];              // zero-init; block0 re-zeroes at end
__device__ float g_pools[NLEV * 32];       // zero-init; block0 re-zeroes at end
__device__ volatile unsigned g_bars[16];   // zeroed by build_all0 each replay

__constant__ int c_LS[NLEV]   = {2048,1024,512,256,128,64,32,16,8,4,2,1,1,1};
__constant__ int c_IOFS[NLEV] = {0,4194304,5242880,5505024,5570560,5586944,5591040,
                                 5592064,5592320,5592384,5592400,5592404,5592405,5592406};

#define FMA2(d, a, b, c) \
    asm("fma.rn.f32x2 %0, %1, %2, %3;" : "=l"(d) : "l"(a), "l"(b), "l"(c))
#define ADD2(d, a, b) \
    asm("add.rn.f32x2 %0, %1, %2;" : "=l"(d) : "l"(a), "l"(b))
#define PACK_DUP(d, a) \
    do { unsigned _u = __float_as_uint(a); \
         asm("mov.b64 %0, {%1, %1};" : "=l"(d) : "r"(_u)); } while (0)

__device__ __forceinline__ float2 upk(unsigned long long a) {
    float2 f; memcpy(&f, &a, 8); return f;
}

// ---- grid-wide barriers (per-epoch counters, reset by next build_all0) -------
__device__ __forceinline__ void gwait(int e, unsigned nb) {
    __syncthreads();
    if (threadIdx.x == 0) {
        __threadfence();
        atomicAdd((unsigned*)&g_bars[e], 1u);
        while (g_bars[e] < nb) __nanosleep(128);
        __threadfence();
    }
    __syncthreads();
}
__device__ __forceinline__ void garrive(int e) {
    __syncthreads();
    __threadfence();
    if (threadIdx.x == 0) atomicAdd((unsigned*)&g_bars[e], 1u);
}

// ---- block compaction step (1024-thread blocks only) -------------------------
__device__ __forceinline__ void emit(int level, bool act, int lin, int posword,
                                     int iofs, unsigned* bitdst) {
    __shared__ int ewcnt[32];
    __shared__ int ewbase[32];
    __shared__ int ebbase;
    int tid = threadIdx.x, wid = tid >> 5, lane = tid & 31;
    unsigned m = __ballot_sync(0xffffffffu, act);
    if (lane == 0) {
        ewcnt[wid] = __popc(m);
        if (bitdst) bitdst[wid] = m;
    }
    __syncthreads();
    if (tid < 32) {
        int cc = ewcnt[tid];
        int x = cc;
        #pragma unroll
        for (int o = 1; o < 32; o <<= 1) {
            int y = __shfl_up_sync(0xffffffffu, x, o);
            if (tid >= o) x += y;
        }
        ewbase[tid] = x - cc;
        if (tid == 31) ebbase = atomicAdd(&g_cnt[level], x);
    }
    __syncthreads();
    int idx = -1;
    if (act) {
        idx = ebbase + ewbase[wid] + __popc(m & ((1u << lane) - 1u));
        if (idx < CAP) g_pos[level * CAP + idx] = posword;
        else idx = -1;
    }
    if (lin >= 0) g_idx[iofs + lin] = idx;
    __syncthreads();
}

__device__ __forceinline__ int getbit(const unsigned* a, int c) {
    return (a[c >> 5] >> (c & 31)) & 1;
}

// ---- build: levels 0..7; zero barrier counters --------------------------------
__global__ __launch_bounds__(1024) void build_all0(const float* __restrict__ mask) {
    if (blockIdx.x == 0 && threadIdx.x < 16) g_bars[threadIdx.x] = 0;

    __shared__ unsigned a0[512];
    __shared__ unsigned a1[128];
    __shared__ unsigned a2[32];
    __shared__ unsigned a3[8];
    __shared__ unsigned a4[32];
    __shared__ unsigned a5[32];
    __shared__ unsigned a6[32];
    int tid = threadIdx.x;
    int tx = blockIdx.x & 15, ty = blockIdx.x >> 4;

    for (int r = 0; r < 16; r++) {
        int c = r * 1024 + tid;
        int li = c >> 7, lj = c & 127;
        int i = ty * 128 + li, j = tx * 128 + lj;
        bool act = (mask[i * 2048 + j] != 0.0f);
        emit(0, act, i * 2048 + j, (i << 16) | j, c_IOFS[0], a0 + r * 32);
    }
    unsigned* bits[8] = {a0, a1, a2, a3, a4, a5, a6, nullptr};
    #pragma unroll
    for (int L = 1; L <= 7; L++) {
        int t = 128 >> L;
        int cells = t * t;
        int chunks = (cells + 1023) >> 10;
        int tprev = t * 2;
        for (int r = 0; r < chunks; r++) {
            int c = r * 1024 + tid;
            bool act = false;
            int lin = -1, pw = 0;
            if (c < cells) {
                int li = c / t, lj = c - li * t;
                int c00 = (2 * li) * tprev + 2 * lj;
                const unsigned* pb = bits[L - 1];
                act = getbit(pb, c00) | getbit(pb, c00 + 1) |
                      getbit(pb, c00 + tprev) | getbit(pb, c00 + tprev + 1);
                int i = ty * t + li, j = tx * t + lj;
                lin = i * (2048 >> L) + j;
                pw = (i << 16) | j;
            }
            emit(L, act, lin, pw, c_IOFS[L], (L < 7) ? (bits[L] + r * 32) : nullptr);
        }
    }
}

// ---- persistent main kernel ---------------------------------------------------
__global__ __launch_bounds__(256, 4) void main_kernel(
    const float* __restrict__ x,  const float* __restrict__ w1,
    const float* __restrict__ ws,
    const float* __restrict__ wm1, const float* __restrict__ bm1,
    const float* __restrict__ wm2, const float* __restrict__ bm2,
    float* __restrict__ out) {
    __shared__ __align__(128) float sW[9216];
    __shared__ float spool[32];
    __shared__ unsigned sball[2];
    int tid = threadIdx.x, bid = blockIdx.x;
    int lane = tid & 31;
    unsigned nb_ = gridDim.x;

    // ================= phase 0: conv1 (all blocks) + build_top (last block) ===
    for (int t = tid; t < 800; t += 256) sW[t] = w1[t];
    if (tid < 32) spool[tid] = 0.f;
    __syncthreads();
    {
        int n = min(g_cnt[0], CAP);
        int gw = (bid * 256 + tid) >> 5;
        int nw = (int)nb_ * 8;
        float pl = 0.f;
        for (int p = gw; p < n; p += nw) {
            int pw = g_pos[p];
            int i = pw >> 16, j = pw & 0xffff;
            float acc = 0.f;
            #pragma unroll
            for (int dy = 0; dy < 5; dy++) {
                int r = i + dy - 2;
                bool rv = (unsigned)r < 2048u;
                #pragma unroll
                for (int dx = 0; dx < 5; dx++) {
                    int cc = j + dx - 2;
                    float xv = (rv && (unsigned)cc < 2048u) ? x[r * 2048 + cc] : 0.f;
                    acc = fmaf(xv, sW[(dy * 5 + dx) * 32 + lane], acc);
                }
            }
            acc = fmaxf(acc, 0.f);
            g_FA[(size_t)p * 32 + lane] = acc;
            pl += acc;
        }
        atomicAdd(&spool[lane], pl);
    }
    if (bid == nb_ - 1) {
        // build_top: levels 8..13 (cells <= 64)
        for (int k = 8; k < NLEV; k++) {
            int s = c_LS[k], sp = c_LS[k - 1];
            int cells = s * s;
            const int* Ip = g_idx + c_IOFS[k - 1];
            bool act = false;
            int pwv = 0;
            if (tid < cells) {
                int i = tid / s, j = tid - i * s;
                #pragma unroll
                for (int di = 0; di < 2; di++)
                    #pragma unroll
                    for (int dj = 0; dj < 2; dj++) {
                        int r = 2 * i + di, cc = 2 * j + dj;
                        if (r < sp && cc < sp && __ldcg(&Ip[r * sp + cc]) >= 0)
                            act = true;
                    }
                pwv = (i << 16) | j;
            }
            unsigned m = __ballot_sync(0xffffffffu, act);
            if (tid == 0)  sball[0] = m;
            if (tid == 32) sball[1] = m;
            __syncthreads();
            int cnt0 = __popc(sball[0]);
            int total = cnt0 + (cells > 32 ? __popc(sball[1]) : 0);
            if (tid == 0) g_cnt[k] = total;
            if (tid < cells) {
                int idx = -1;
                if (act) {
                    idx = (tid < 32 ? 0 : cnt0) + __popc(m & ((1u << (tid & 31)) - 1u));
                    g_pos[k * CAP + idx] = pwv;
                }
                g_idx[c_IOFS[k] + tid] = idx;
            }
            __syncthreads();
        }
    }
    __syncthreads();
    if (tid < 32) atomicAdd(&g_pools[tid], spool[tid]);
    __syncthreads();

    // ================= levels 1..7: sparse conv, 1 pos x 8 ch / thread ========
    // Balanced contiguous per-block chunks (fix for 2-tile stragglers).
    int pid = tid >> 2;            // 0..63 position within 64-pos step
    int chb = (tid & 3) * 8;       // 8 output channels
    #pragma unroll 1
    for (int L = 1; L <= 7; L++) {
        {   // stage this level's weights + zero spool before the barrier
            const float4* src = (const float4*)(ws + (size_t)(L - 1) * 9216);
            float4* dst = (float4*)sW;
            #pragma unroll
            for (int t = 0; t < 9; t++) dst[tid + t * 256] = src[tid + t * 256];
        }
        if (tid < 32) spool[tid] = 0.f;
        gwait(L - 1, nb_);         // previous phase complete grid-wide

        const float* __restrict__ Fp = (L & 1) ? g_FA : g_FB;
        float* __restrict__ Fc = (L & 1) ? g_FB : g_FA;
        int sp = c_LS[L - 1];
        const int* __restrict__ Ip = g_idx + c_IOFS[L - 1];
        const int* __restrict__ posl = g_pos + L * CAP;
        int n = min(g_cnt[L], CAP);

        int chunk = (n + (int)nb_ - 1) / (int)nb_;   // positions per block
        int start = bid * chunk;
        int pend  = min(start + chunk, n);

        unsigned long long pool[4] = {0ull, 0ull, 0ull, 0ull};
        for (int base = start; base < pend; base += 64) {
            int p = base + pid;
            int pw = (p < pend) ? posl[p] : -1;
            int pi = pw >> 16, pj = pw & 0xffff;
            unsigned long long acc[4] = {0ull, 0ull, 0ull, 0ull};

            // one-ahead neighbor index prefetch
            int nbr_next = -1;
            if (pw >= 0) {
                int r = 2 * pi - 1, c = 2 * pj - 1;
                if ((unsigned)r < (unsigned)sp && (unsigned)c < (unsigned)sp)
                    nbr_next = Ip[r * sp + c];
            }
            #pragma unroll 1
            for (int d = 0; d < 9; d++) {
                int nbr = nbr_next;
                if (d < 8 && pw >= 0) {
                    int dn = d + 1;
                    int r = 2 * pi + dn / 3 - 1;
                    int c = 2 * pj + dn % 3 - 1;
                    nbr_next = -1;
                    if ((unsigned)r < (unsigned)sp && (unsigned)c < (unsigned)sp)
                        nbr_next = Ip[r * sp + c];
                } else if (d < 8) nbr_next = -1;
                bool v = nbr >= 0;
                if (!__ballot_sync(0xffffffffu, v)) continue;   // warp tap skip
                const float* ap = Fp + (size_t)max(nbr, 0) * 32;
                const float* wd = sW + d * 1024 + chb;
                #pragma unroll
                for (int q = 0; q < 8; q++) {
                    float4 xq = v ? __ldcg((const float4*)(ap + q * 4))
                                  : make_float4(0.f, 0.f, 0.f, 0.f);
                    #pragma unroll
                    for (int j2 = 0; j2 < 4; j2++) {
                        float e = (j2 == 0) ? xq.x : (j2 == 1) ? xq.y
                                : (j2 == 2) ? xq.z : xq.w;
                        unsigned long long A;
                        PACK_DUP(A, e);
                        const ulonglong2* w2 =
                            (const ulonglong2*)(wd + (q * 4 + j2) * 32);
                        ulonglong2 wa = w2[0];
                        ulonglong2 wb = w2[1];
                        FMA2(acc[0], A, wa.x, acc[0]);
                        FMA2(acc[1], A, wa.y, acc[1]);
                        FMA2(acc[2], A, wb.x, acc[2]);
                        FMA2(acc[3], A, wb.y, acc[3]);
                    }
                }
            }
            // relu (packed), pool, store 8 channels
            #pragma unroll
            for (int i2 = 0; i2 < 4; i2++) {
                float2 f = upk(acc[i2]);
                f.x = fmaxf(f.x, 0.f); f.y = fmaxf(f.y, 0.f);
                unsigned long long P;
                asm("mov.b64 %0, {%1, %2};" : "=l"(P)
                    : "r"(__float_as_uint(f.x)), "r"(__float_as_uint(f.y)));
                ADD2(pool[i2], P, pool[i2]);
                acc[i2] = P;
            }
            if (p < pend) {
                ulonglong2* dst = (ulonglong2*)(Fc + (size_t)p * 32 + chb);
                dst[0] = make_ulonglong2(acc[0], acc[1]);
                dst[1] = make_ulonglong2(acc[2], acc[3]);
            }
        }
        // pool: butterfly (offsets 16,8,4 preserve lane&3 channel groups)
        #pragma unroll
        for (int i2 = 0; i2 < 4; i2++) {
            #pragma unroll
            for (int off = 16; off >= 4; off >>= 1) {
                unsigned long long o = __shfl_xor_sync(0xffffffffu, pool[i2], off);
                ADD2(pool[i2], o, pool[i2]);
            }
        }
        if (lane < 4) {
            #pragma unroll
            for (int i2 = 0; i2 < 4; i2++) {
                float2 f = upk(pool[i2]);
                atomicAdd(&spool[chb + 2 * i2],     f.x);
                atomicAdd(&spool[chb + 2 * i2 + 1], f.y);
            }
        }
        __syncthreads();
        if (tid < 32) atomicAdd(&g_pools[L * 32 + tid], spool[tid]);
        __syncthreads();
    }

    // ================= tail: 8 blocks, mini grid barriers ======================
    if (bid >= 8) { garrive(7); return; }
    gwait(7, nb_);

    int wid = tid >> 5;
    for (int k = 8; k < NLEV; k++) {
        int n = min(g_cnt[k], CAP);
        int sp = c_LS[k - 1];
        const int* Ip = g_idx + c_IOFS[k - 1];
        const float* FpT = (k & 1) ? g_FA : g_FB;
        float* FcT = (k & 1) ? g_FB : g_FA;
        const float* W = ws + (size_t)(k - 1) * 9216;
        if (tid < 32) spool[tid] = 0.f;
        __syncthreads();
        float pl = 0.f;
        for (int p = bid * 8 + wid; p < n; p += 64) {   // 8 blocks x 8 warps
            int pw = g_pos[k * CAP + p];
            int pi = pw >> 16, pj = pw & 0xffff;
            float acc = 0.f;
            for (int d = 0; d < 9; d++) {
                int r = 2 * pi + d / 3 - 1;
                int cc = 2 * pj + d % 3 - 1;
                if ((unsigned)r < (unsigned)sp && (unsigned)cc < (unsigned)sp) {
                    int nbv = Ip[r * sp + cc];
                    if (nbv >= 0) {
                        float row = __ldcg(&FpT[(size_t)nbv * 32 + lane]);
                        const float* wd = W + d * 1024;
                        #pragma unroll
                        for (int ci = 0; ci < 32; ci++)
                            acc = fmaf(__shfl_sync(0xffffffffu, row, ci),
                                       wd[ci * 32 + lane], acc);
                    }
                }
            }
            acc = fmaxf(acc, 0.f);
            FcT[(size_t)p * 32 + lane] = acc;
            pl += acc;
        }
        atomicAdd(&spool[lane], pl);
        __syncthreads();
        if (tid < 32) atomicAdd(&g_pools[k * 32 + tid], spool[tid]);
        gwait(8 + (k - 8), 8);     // 8-block barrier before next level
    }

    if (bid != 0) return;

    // MLP: feat[448] -> 256 relu -> 128 (reuse sW as sf/sh); block 0 only
    float* sf = sW;
    float* sh = sW + 448;
    for (int i = tid; i < 448; i += 256) {
        int k = i >> 5;
        float cnt = (float)max(g_cnt[k], 1);
        sf[i] = g_pools[i] / cnt;
    }
    __syncthreads();
    {
        float acc = bm1[tid];
        #pragma unroll 4
        for (int i = 0; i < 448; i++) acc = fmaf(sf[i], wm1[i * 256 + tid], acc);
        sh[tid] = fmaxf(acc, 0.f);
    }
    __syncthreads();
    if (tid < 128) {
        float acc = bm2[tid];
        #pragma unroll 4
        for (int j = 0; j < 256; j++) acc = fmaf(sh[j], wm2[j * 128 + tid], acc);
        out[tid] = acc;
    }

    // re-zero state for next replay (bars reset by next build_all0)
    __syncthreads();
    for (int i = tid; i < NLEV * 32; i += 256) g_pools[i] = 0.f;
    if (tid < NLEV) g_cnt[tid] = 0;
}

// ---- host launch ---------------------------------------------------------------
extern "C" void kernel_launch(void* const* d_in, const int* in_sizes, int n_in,
                              void* d_out, int out_size) {
    const float* x    = (const float*)d_in[0];
    const float* mask = (const float*)d_in[1];
    const float* w1   = (const float*)d_in[2];
    const float* ws   = (const float*)d_in[3];
    const float* wm1  = (const float*)d_in[4];
    const float* bm1  = (const float*)d_in[5];
    const float* wm2  = (const float*)d_in[6];
    const float* bm2  = (const float*)d_in[7];
    float* out = (float*)d_out;

    build_all0<<<256, 1024>>>(mask);

    int occ = 0, sms = 0;
    cudaOccupancyMaxActiveBlocksPerMultiprocessor(&occ, main_kernel, 256, 0);
    cudaDeviceGetAttribute(&sms, cudaDevAttrMultiProcessorCount, 0);
    int grid = occ * sms;
    if (grid > 592) grid = 592;
    if (grid < 8) grid = 8;

    main_kernel<<<grid, 256>>>(x, w1, ws, wm1, bm1, wm2, bm2, out);
}

// round 14
// speedup vs baseline: 1.3917x; 1.0130x over previous
#include <cuda_runtime.h>
#include <cuda_pipeline.h>
#include <cstdint>
#include <cstring>

// ============================================================================
// Sparse masked CNN pyramid (14 levels) + MLP head — round 14.
// = R13 (best, 286.8us) with the convk inner loop converted to a per-warp
//   3-stage cp.async pipeline (taps d+1, d+2 staged in smem while FMAing d).
// ============================================================================

#define CAP 131072
#define NLEV 14
#define IDX_TOTAL 5592407

__device__ __align__(16) float g_FA[CAP * 32];
__device__ __align__(16) float g_FB[CAP * 32];
__device__ int   g_idx[IDX_TOTAL];
__device__ int   g_pos[NLEV * CAP];
__device__ int   g_cnt[NLEV];              // zero-init; block0 re-zeroes at end
__device__ float g_pools[NLEV * 32];       // zero-init; block0 re-zeroes at end
__device__ volatile unsigned g_bars[16];   // zeroed by build_all0 each replay

__constant__ int c_LS[NLEV]   = {2048,1024,512,256,128,64,32,16,8,4,2,1,1,1};
__constant__ int c_IOFS[NLEV] = {0,4194304,5242880,5505024,5570560,5586944,5591040,
                                 5592064,5592320,5592384,5592400,5592404,5592405,5592406};

// dynamic smem layout (floats): sW[9216] | sA[8 warps][3 bufs][8 pos][36] | spool[32] | sball[2]
#define SA_OFF   9216
#define SA_WARP  (3 * 288)
#define SPOOL_OFF (SA_OFF + 8 * SA_WARP)
#define SBALL_OFF (SPOOL_OFF + 32)
#define SMEM_MAIN ((SBALL_OFF + 8) * 4)

#define FMA2(d, a, b, c) \
    asm("fma.rn.f32x2 %0, %1, %2, %3;" : "=l"(d) : "l"(a), "l"(b), "l"(c))
#define ADD2(d, a, b) \
    asm("add.rn.f32x2 %0, %1, %2;" : "=l"(d) : "l"(a), "l"(b))
#define PACK_DUP(d, a) \
    do { unsigned _u = __float_as_uint(a); \
         asm("mov.b64 %0, {%1, %1};" : "=l"(d) : "r"(_u)); } while (0)

__device__ __forceinline__ float2 upk(unsigned long long a) {
    float2 f; memcpy(&f, &a, 8); return f;
}

// ---- grid-wide barriers (per-epoch counters, reset by next build_all0) -------
__device__ __forceinline__ void gwait(int e, unsigned nb) {
    __syncthreads();
    if (threadIdx.x == 0) {
        __threadfence();
        atomicAdd((unsigned*)&g_bars[e], 1u);
        while (g_bars[e] < nb) __nanosleep(128);
        __threadfence();
    }
    __syncthreads();
}
__device__ __forceinline__ void garrive(int e) {
    __syncthreads();
    __threadfence();
    if (threadIdx.x == 0) atomicAdd((unsigned*)&g_bars[e], 1u);
}

// ---- block compaction step (1024-thread blocks only) -------------------------
__device__ __forceinline__ void emit(int level, bool act, int lin, int posword,
                                     int iofs, unsigned* bitdst) {
    __shared__ int ewcnt[32];
    __shared__ int ewbase[32];
    __shared__ int ebbase;
    int tid = threadIdx.x, wid = tid >> 5, lane = tid & 31;
    unsigned m = __ballot_sync(0xffffffffu, act);
    if (lane == 0) {
        ewcnt[wid] = __popc(m);
        if (bitdst) bitdst[wid] = m;
    }
    __syncthreads();
    if (tid < 32) {
        int cc = ewcnt[tid];
        int x = cc;
        #pragma unroll
        for (int o = 1; o < 32; o <<= 1) {
            int y = __shfl_up_sync(0xffffffffu, x, o);
            if (tid >= o) x += y;
        }
        ewbase[tid] = x - cc;
        if (tid == 31) ebbase = atomicAdd(&g_cnt[level], x);
    }
    __syncthreads();
    int idx = -1;
    if (act) {
        idx = ebbase + ewbase[wid] + __popc(m & ((1u << lane) - 1u));
        if (idx < CAP) g_pos[level * CAP + idx] = posword;
        else idx = -1;
    }
    if (lin >= 0) g_idx[iofs + lin] = idx;
    __syncthreads();
}

__device__ __forceinline__ int getbit(const unsigned* a, int c) {
    return (a[c >> 5] >> (c & 31)) & 1;
}

// ---- build: levels 0..7; zero barrier counters --------------------------------
__global__ __launch_bounds__(1024) void build_all0(const float* __restrict__ mask) {
    if (blockIdx.x == 0 && threadIdx.x < 16) g_bars[threadIdx.x] = 0;

    __shared__ unsigned a0[512];
    __shared__ unsigned a1[128];
    __shared__ unsigned a2[32];
    __shared__ unsigned a3[8];
    __shared__ unsigned a4[32];
    __shared__ unsigned a5[32];
    __shared__ unsigned a6[32];
    int tid = threadIdx.x;
    int tx = blockIdx.x & 15, ty = blockIdx.x >> 4;

    for (int r = 0; r < 16; r++) {
        int c = r * 1024 + tid;
        int li = c >> 7, lj = c & 127;
        int i = ty * 128 + li, j = tx * 128 + lj;
        bool act = (mask[i * 2048 + j] != 0.0f);
        emit(0, act, i * 2048 + j, (i << 16) | j, c_IOFS[0], a0 + r * 32);
    }
    unsigned* bits[8] = {a0, a1, a2, a3, a4, a5, a6, nullptr};
    #pragma unroll
    for (int L = 1; L <= 7; L++) {
        int t = 128 >> L;
        int cells = t * t;
        int chunks = (cells + 1023) >> 10;
        int tprev = t * 2;
        for (int r = 0; r < chunks; r++) {
            int c = r * 1024 + tid;
            bool act = false;
            int lin = -1, pw = 0;
            if (c < cells) {
                int li = c / t, lj = c - li * t;
                int c00 = (2 * li) * tprev + 2 * lj;
                const unsigned* pb = bits[L - 1];
                act = getbit(pb, c00) | getbit(pb, c00 + 1) |
                      getbit(pb, c00 + tprev) | getbit(pb, c00 + tprev + 1);
                int i = ty * t + li, j = tx * t + lj;
                lin = i * (2048 >> L) + j;
                pw = (i << 16) | j;
            }
            emit(L, act, lin, pw, c_IOFS[L], (L < 7) ? (bits[L] + r * 32) : nullptr);
        }
    }
}

// ---- persistent main kernel ---------------------------------------------------
__global__ __launch_bounds__(256) void main_kernel(
    const float* __restrict__ x,  const float* __restrict__ w1,
    const float* __restrict__ ws,
    const float* __restrict__ wm1, const float* __restrict__ bm1,
    const float* __restrict__ wm2, const float* __restrict__ bm2,
    float* __restrict__ out) {
    extern __shared__ __align__(16) float smem[];
    float* sW = smem;
    float* sA = smem + SA_OFF;
    float* spool = smem + SPOOL_OFF;
    unsigned* sball = (unsigned*)(smem + SBALL_OFF);

    int tid = threadIdx.x, bid = blockIdx.x;
    int lane = tid & 31;
    unsigned nb_ = gridDim.x;

    // ================= phase 0: conv1 (all blocks) + build_top (last block) ===
    for (int t = tid; t < 800; t += 256) sW[t] = w1[t];
    if (tid < 32) spool[tid] = 0.f;
    __syncthreads();
    {
        int n = min(g_cnt[0], CAP);
        int gw = (bid * 256 + tid) >> 5;
        int nw = (int)nb_ * 8;
        float pl = 0.f;
        for (int p = gw; p < n; p += nw) {
            int pw = g_pos[p];
            int i = pw >> 16, j = pw & 0xffff;
            float acc = 0.f;
            #pragma unroll
            for (int dy = 0; dy < 5; dy++) {
                int r = i + dy - 2;
                bool rv = (unsigned)r < 2048u;
                #pragma unroll
                for (int dx = 0; dx < 5; dx++) {
                    int cc = j + dx - 2;
                    float xv = (rv && (unsigned)cc < 2048u) ? x[r * 2048 + cc] : 0.f;
                    acc = fmaf(xv, sW[(dy * 5 + dx) * 32 + lane], acc);
                }
            }
            acc = fmaxf(acc, 0.f);
            g_FA[(size_t)p * 32 + lane] = acc;
            pl += acc;
        }
        atomicAdd(&spool[lane], pl);
    }
    if (bid == nb_ - 1) {
        for (int k = 8; k < NLEV; k++) {
            int s = c_LS[k], sp = c_LS[k - 1];
            int cells = s * s;
            const int* Ip = g_idx + c_IOFS[k - 1];
            bool act = false;
            int pwv = 0;
            if (tid < cells) {
                int i = tid / s, j = tid - i * s;
                #pragma unroll
                for (int di = 0; di < 2; di++)
                    #pragma unroll
                    for (int dj = 0; dj < 2; dj++) {
                        int r = 2 * i + di, cc = 2 * j + dj;
                        if (r < sp && cc < sp && __ldcg(&Ip[r * sp + cc]) >= 0)
                            act = true;
                    }
                pwv = (i << 16) | j;
            }
            unsigned m = __ballot_sync(0xffffffffu, act);
            if (tid == 0)  sball[0] = m;
            if (tid == 32) sball[1] = m;
            __syncthreads();
            int cnt0 = __popc(sball[0]);
            int total = cnt0 + (cells > 32 ? __popc(sball[1]) : 0);
            if (tid == 0) g_cnt[k] = total;
            if (tid < cells) {
                int idx = -1;
                if (act) {
                    idx = (tid < 32 ? 0 : cnt0) + __popc(m & ((1u << (tid & 31)) - 1u));
                    g_pos[k * CAP + idx] = pwv;
                }
                g_idx[c_IOFS[k] + tid] = idx;
            }
            __syncthreads();
        }
    }
    __syncthreads();
    if (tid < 32) atomicAdd(&g_pools[tid], spool[tid]);
    __syncthreads();

    // ================= levels 1..7: cp.async-pipelined sparse conv =============
    int pid  = tid >> 2;           // 0..63 position within 64-pos step
    int chb  = (tid & 3) * 8;      // 8 output channels
    int w    = tid >> 5;           // warp id 0..7
    int srow = (lane >> 2);        // staging row (0..7) for this lane's quad
    int cch  = lane & 3;           // staging chunk (0..3) this lane copies
    float* sAw = sA + w * SA_WARP; // this warp's 3 staging buffers

    #pragma unroll 1
    for (int L = 1; L <= 7; L++) {
        {   // stage this level's weights + zero spool before the barrier
            const float4* src = (const float4*)(ws + (size_t)(L - 1) * 9216);
            float4* dst = (float4*)sW;
            #pragma unroll
            for (int t = 0; t < 9; t++) dst[tid + t * 256] = src[tid + t * 256];
        }
        if (tid < 32) spool[tid] = 0.f;
        gwait(L - 1, nb_);

        const float* __restrict__ Fp = (L & 1) ? g_FA : g_FB;
        float* __restrict__ Fc = (L & 1) ? g_FB : g_FA;
        int sp = c_LS[L - 1];
        const int* __restrict__ Ip = g_idx + c_IOFS[L - 1];
        const int* __restrict__ posl = g_pos + L * CAP;
        int n = min(g_cnt[L], CAP);

        int chunk = (n + (int)nb_ - 1) / (int)nb_;
        int start = bid * chunk;
        int pend  = min(start + chunk, n);

        unsigned long long pool[4] = {0ull, 0ull, 0ull, 0ull};
        for (int base = start; base < pend; base += 64) {
            int p = base + pid;
            int pw = (p < pend) ? posl[p] : -1;
            int pi = pw >> 16, pj = pw & 0xffff;

            // all 9 neighbor indices up-front (registers; 9 parallel LDGs)
            int nb[9];
            #pragma unroll
            for (int d = 0; d < 9; d++) {
                int a = -1;
                if (pw >= 0) {
                    int r = 2 * pi + d / 3 - 1;
                    int c = 2 * pj + d % 3 - 1;
                    if ((unsigned)r < (unsigned)sp && (unsigned)c < (unsigned)sp)
                        a = Ip[r * sp + c];
                }
                nb[d] = a;
            }

            // prime taps 0,1,2 into buffers 0,1,2
            #pragma unroll
            for (int d0 = 0; d0 < 3; d0++) {
                int nn = nb[d0];
                const float* src = Fp + (size_t)max(nn, 0) * 32 + cch * 4;
                float* dst = sAw + d0 * 288 + srow * 36 + cch * 4;
                size_t z = (nn >= 0) ? 0 : 16;
                __pipeline_memcpy_async(dst, src, 16, z);
                __pipeline_memcpy_async(dst + 16, src + 16, 16, z);
                __pipeline_commit();
            }

            unsigned long long acc[4] = {0ull, 0ull, 0ull, 0ull};
            #pragma unroll
            for (int d = 0; d < 9; d++) {
                if (d <= 6)      __pipeline_wait_prior(2);
                else if (d == 7) __pipeline_wait_prior(1);
                else             __pipeline_wait_prior(0);
                __syncwarp();
                if (__ballot_sync(0xffffffffu, nb[d] >= 0)) {
                    const float* row = sAw + (d % 3) * 288 + srow * 36;
                    const float* wd = sW + d * 1024 + chb;
                    #pragma unroll
                    for (int q = 0; q < 8; q++) {
                        float4 xq = *(const float4*)(row + q * 4);
                        #pragma unroll
                        for (int j2 = 0; j2 < 4; j2++) {
                            float e = (j2 == 0) ? xq.x : (j2 == 1) ? xq.y
                                    : (j2 == 2) ? xq.z : xq.w;
                            unsigned long long A;
                            PACK_DUP(A, e);
                            const ulonglong2* w2 =
                                (const ulonglong2*)(wd + (q * 4 + j2) * 32);
                            ulonglong2 wa = w2[0];
                            ulonglong2 wb = w2[1];
                            FMA2(acc[0], A, wa.x, acc[0]);
                            FMA2(acc[1], A, wa.y, acc[1]);
                            FMA2(acc[2], A, wb.x, acc[2]);
                            FMA2(acc[3], A, wb.y, acc[3]);
                        }
                    }
                }
                __syncwarp();          // all lanes done reading buf (d%3)
                if (d + 3 <= 8) {      // refill it with tap d+3
                    int nn = nb[d + 3];
                    const float* src = Fp + (size_t)max(nn, 0) * 32 + cch * 4;
                    float* dst = sAw + (d % 3) * 288 + srow * 36 + cch * 4;
                    size_t z = (nn >= 0) ? 0 : 16;
                    __pipeline_memcpy_async(dst, src, 16, z);
                    __pipeline_memcpy_async(dst + 16, src + 16, 16, z);
                    __pipeline_commit();
                }
            }

            // relu (packed), pool, store 8 channels
            #pragma unroll
            for (int i2 = 0; i2 < 4; i2++) {
                float2 f = upk(acc[i2]);
                f.x = fmaxf(f.x, 0.f); f.y = fmaxf(f.y, 0.f);
                unsigned long long P;
                asm("mov.b64 %0, {%1, %2};" : "=l"(P)
                    : "r"(__float_as_uint(f.x)), "r"(__float_as_uint(f.y)));
                ADD2(pool[i2], P, pool[i2]);
                acc[i2] = P;
            }
            if (p < pend) {
                ulonglong2* dst = (ulonglong2*)(Fc + (size_t)p * 32 + chb);
                dst[0] = make_ulonglong2(acc[0], acc[1]);
                dst[1] = make_ulonglong2(acc[2], acc[3]);
            }
        }
        // pool: butterfly (offsets 16,8,4 preserve lane&3 channel groups)
        #pragma unroll
        for (int i2 = 0; i2 < 4; i2++) {
            #pragma unroll
            for (int off = 16; off >= 4; off >>= 1) {
                unsigned long long o = __shfl_xor_sync(0xffffffffu, pool[i2], off);
                ADD2(pool[i2], o, pool[i2]);
            }
        }
        if (lane < 4) {
            #pragma unroll
            for (int i2 = 0; i2 < 4; i2++) {
                float2 f = upk(pool[i2]);
                atomicAdd(&spool[chb + 2 * i2],     f.x);
                atomicAdd(&spool[chb + 2 * i2 + 1], f.y);
            }
        }
        __syncthreads();
        if (tid < 32) atomicAdd(&g_pools[L * 32 + tid], spool[tid]);
        __syncthreads();
    }

    // ================= tail: 8 blocks, mini grid barriers ======================
    if (bid >= 8) { garrive(7); return; }
    gwait(7, nb_);

    int wid = tid >> 5;
    for (int k = 8; k < NLEV; k++) {
        int n = min(g_cnt[k], CAP);
        int sp = c_LS[k - 1];
        const int* Ip = g_idx + c_IOFS[k - 1];
        const float* FpT = (k & 1) ? g_FA : g_FB;
        float* FcT = (k & 1) ? g_FB : g_FA;
        const float* W = ws + (size_t)(k - 1) * 9216;
        if (tid < 32) spool[tid] = 0.f;
        __syncthreads();
        float pl = 0.f;
        for (int p = bid * 8 + wid; p < n; p += 64) {
            int pw = g_pos[k * CAP + p];
            int pi = pw >> 16, pj = pw & 0xffff;
            float acc = 0.f;
            for (int d = 0; d < 9; d++) {
                int r = 2 * pi + d / 3 - 1;
                int cc = 2 * pj + d % 3 - 1;
                if ((unsigned)r < (unsigned)sp && (unsigned)cc < (unsigned)sp) {
                    int nbv = Ip[r * sp + cc];
                    if (nbv >= 0) {
                        float row = __ldcg(&FpT[(size_t)nbv * 32 + lane]);
                        const float* wd = W + d * 1024;
                        #pragma unroll
                        for (int ci = 0; ci < 32; ci++)
                            acc = fmaf(__shfl_sync(0xffffffffu, row, ci),
                                       wd[ci * 32 + lane], acc);
                    }
                }
            }
            acc = fmaxf(acc, 0.f);
            FcT[(size_t)p * 32 + lane] = acc;
            pl += acc;
        }
        atomicAdd(&spool[lane], pl);
        __syncthreads();
        if (tid < 32) atomicAdd(&g_pools[k * 32 + tid], spool[tid]);
        gwait(8 + (k - 8), 8);
    }

    if (bid != 0) return;

    // MLP: feat[448] -> 256 relu -> 128 (reuse sW as sf/sh); block 0 only
    float* sf = sW;
    float* sh = sW + 448;
    for (int i = tid; i < 448; i += 256) {
        int k = i >> 5;
        float cnt = (float)max(g_cnt[k], 1);
        sf[i] = g_pools[i] / cnt;
    }
    __syncthreads();
    {
        float acc = bm1[tid];
        #pragma unroll 4
        for (int i = 0; i < 448; i++) acc = fmaf(sf[i], wm1[i * 256 + tid], acc);
        sh[tid] = fmaxf(acc, 0.f);
    }
    __syncthreads();
    if (tid < 128) {
        float acc = bm2[tid];
        #pragma unroll 4
        for (int j = 0; j < 256; j++) acc = fmaf(sh[j], wm2[j * 128 + tid], acc);
        out[tid] = acc;
    }

    // re-zero state for next replay (bars reset by next build_all0)
    __syncthreads();
    for (int i = tid; i < NLEV * 32; i += 256) g_pools[i] = 0.f;
    if (tid < NLEV) g_cnt[tid] = 0;
}

// ---- host launch ---------------------------------------------------------------
extern "C" void kernel_launch(void* const* d_in, const int* in_sizes, int n_in,
                              void* d_out, int out_size) {
    const float* x    = (const float*)d_in[0];
    const float* mask = (const float*)d_in[1];
    const float* w1   = (const float*)d_in[2];
    const float* ws   = (const float*)d_in[3];
    const float* wm1  = (const float*)d_in[4];
    const float* bm1  = (const float*)d_in[5];
    const float* wm2  = (const float*)d_in[6];
    const float* bm2  = (const float*)d_in[7];
    float* out = (float*)d_out;

    cudaFuncSetAttribute((const void*)main_kernel,
                         cudaFuncAttributeMaxDynamicSharedMemorySize, SMEM_MAIN);

    build_all0<<<256, 1024>>>(mask);

    int occ = 0, sms = 0;
    cudaOccupancyMaxActiveBlocksPerMultiprocessor(&occ, main_kernel, 256, SMEM_MAIN);
    cudaDeviceGetAttribute(&sms, cudaDevAttrMultiProcessorCount, 0);
    int grid = occ * sms;
    if (grid > 592) grid = 592;
    if (grid < 8) grid = 8;

    main_kernel<<<grid, 256, SMEM_MAIN>>>(x, w1, ws, wm1, bm1, wm2, bm2, out);
}